// round 10
// baseline (speedup 1.0000x reference)
#include <cuda_runtime.h>
#include <math.h>

#define NN 100000
#define EE 1600000
#define DD 128
#define HID 32

typedef unsigned long long ull;

// ---------------- scratch (device globals) ------------------------------------
__device__ int   g_is64;
__device__ int   g_deg[NN];
__device__ float g_dinv[NN];
__device__ int   g_off[NN + 1];
__device__ int   g_cur[NN];
__device__ int   g_src32[EE];
__device__ int   g_dst32[EE];
__device__ int   g_srcs[EE];                // CSR: prescaled src element offsets (s*32)
__device__ ulonglong2 g_y2v[(size_t)NN * 16];   // (z,h) packed pairs; 16B-aligned
#define g_y2 ((ull*)g_y2v)
__device__ float g_H[(size_t)NN * HID];
__device__ float g_WT[64 * DD];             // WeffT[j][k], j: 0..31=z, 32..63=h
__device__ ull   g_beff2[32];               // packed (bz_eff, bh_eff)
__device__ int   g_bsum[128];

// ---------------- f32x2 helpers -----------------------------------------------
__device__ __forceinline__ ull pack2(float a, float b) {
    ull r; asm("mov.b64 %0, {%1, %2};" : "=l"(r) : "f"(a), "f"(b)); return r;
}
__device__ __forceinline__ void unpack2(ull v, float& a, float& b) {
    asm("mov.b64 {%0, %1}, %2;" : "=f"(a), "=f"(b) : "l"(v));
}
__device__ __forceinline__ ull fma2(ull a, ull b, ull c) {
    ull d; asm("fma.rn.f32x2 %0, %1, %2, %3;" : "=l"(d) : "l"(a), "l"(b), "l"(c)); return d;
}
__device__ __forceinline__ ull mul2(ull a, ull b) {
    ull d; asm("mul.rn.f32x2 %0, %1, %2;" : "=l"(d) : "l"(a), "l"(b)); return d;
}
__device__ __forceinline__ ull add2(ull a, ull b) {
    ull d; asm("add.rn.f32x2 %0, %1, %2;" : "=l"(d) : "l"(a), "l"(b)); return d;
}

__device__ __forceinline__ int edge_at(const void* ei, int is64, long long idx) {
    return is64 ? (int)((const long long*)ei)[idx] : ((const int*)ei)[idx];
}

// ---------------- prep: detect + deg init + Weff^T + beff ---------------------
__global__ void k_prep(const void* ei,
                       const float* Wz, const float* Wh,
                       const float* Lzw, const float* Lhw,
                       const float* bz, const float* bh,
                       const float* Lzb, const float* Lhb) {
    int b = blockIdx.x, t = threadIdx.x;
    if (b < 391) {
        int i = b * 256 + t;
        if (i < NN) g_deg[i] = 1;           // self loop
    } else if (b == 391) {
        __shared__ int s;
        if (t == 0) s = 1;
        __syncthreads();
        const long long* p = (const long long*)ei;
        for (int i = t; i < 4096; i += 256)
            if ((p[i] >> 32) != 0) s = 0;
        __syncthreads();
        if (t == 0) g_is64 = s;
    } else {
        int idx = (b - 392) * 256 + t;      // [0, 8192)
        int k = idx >> 6, j = idx & 63;
        float acc = 0.f;
        if (j < HID) {
            for (int m = 0; m < HID; m++) acc = fmaf(Wz[k * HID + m], Lzw[m * HID + j], acc);
        } else {
            int jj = j - HID;
            for (int m = 0; m < HID; m++) acc = fmaf(Wh[k * HID + m], Lhw[m * HID + jj], acc);
        }
        g_WT[j * DD + k] = acc;             // transposed store
        if (b == 392 && t < 32) {
            float az = Lzb[t], ah = Lhb[t];
            for (int m = 0; m < HID; m++) {
                az = fmaf(bz[m], Lzw[m * HID + t], az);
                ah = fmaf(bh[m], Lhw[m * HID + t], ah);
            }
            g_beff2[t] = pack2(az, ah);
        }
    }
}

// ---------------- fused: GEMM (blocks [0,GEMMB)) + edge conv/degree ----------
#define GEMMB 3125
#define DEGB  6250
__global__ void k_main1(const float* __restrict__ x, const void* __restrict__ ei) {
    __shared__ float sWT[64 * 130];         // padded rows: stride 130 floats
    int t = threadIdx.x;
    if (blockIdx.x < GEMMB) {
        for (int i = t; i < 64 * 128; i += 256) {
            int j = i >> 7, k = i & 127;
            sWT[j * 130 + k] = g_WT[i];
        }
        __syncthreads();
        int warp = t >> 5, lane = t & 31;
        int n0 = (blockIdx.x * 8 + warp) * 4;       // 4 nodes per warp
        if (n0 >= NN) return;
        const float4* x4 = (const float4*)x;
        ull az[4] = {0, 0, 0, 0}, ah[4] = {0, 0, 0, 0};
        const ull* wzr = (const ull*)&sWT[lane * 130];
        const ull* whr = (const ull*)&sWT[(lane + 32) * 130];
#pragma unroll 4
        for (int k4 = 0; k4 < 32; k4++) {
            float4 a0 = x4[(size_t)(n0 + 0) * 32 + k4];
            float4 a1 = x4[(size_t)(n0 + 1) * 32 + k4];
            float4 a2 = x4[(size_t)(n0 + 2) * 32 + k4];
            float4 a3 = x4[(size_t)(n0 + 3) * 32 + k4];
            ull wz0 = wzr[k4 * 2], wz1 = wzr[k4 * 2 + 1];
            ull wh0 = whr[k4 * 2], wh1 = whr[k4 * 2 + 1];
            const ull* p0 = (const ull*)&a0; const ull* p1 = (const ull*)&a1;
            const ull* p2 = (const ull*)&a2; const ull* p3 = (const ull*)&a3;
            az[0] = fma2(p0[0], wz0, az[0]); az[0] = fma2(p0[1], wz1, az[0]);
            ah[0] = fma2(p0[0], wh0, ah[0]); ah[0] = fma2(p0[1], wh1, ah[0]);
            az[1] = fma2(p1[0], wz0, az[1]); az[1] = fma2(p1[1], wz1, az[1]);
            ah[1] = fma2(p1[0], wh0, ah[1]); ah[1] = fma2(p1[1], wh1, ah[1]);
            az[2] = fma2(p2[0], wz0, az[2]); az[2] = fma2(p2[1], wz1, az[2]);
            ah[2] = fma2(p2[0], wh0, ah[2]); ah[2] = fma2(p2[1], wh1, ah[2]);
            az[3] = fma2(p3[0], wz0, az[3]); az[3] = fma2(p3[1], wz1, az[3]);
            ah[3] = fma2(p3[0], wh0, ah[3]); ah[3] = fma2(p3[1], wh1, ah[3]);
        }
#pragma unroll
        for (int i = 0; i < 4; i++) {
            float zl, zh, hl, hh;
            unpack2(az[i], zl, zh);
            unpack2(ah[i], hl, hh);
            g_y2[(size_t)(n0 + i) * 32 + lane] = pack2(zl + zh, hl + hh);
        }
    } else {
        int is64 = g_is64;
        int e = (blockIdx.x - GEMMB) * 256 + t;
        if (e < EE) {
            int s = edge_at(ei, is64, e);
            int d = edge_at(ei, is64, (long long)EE + e);
            g_src32[e] = s;
            g_dst32[e] = d;
            atomicAdd(&g_deg[d], 1);
        }
    }
}

// ---------------- phase-1 scan: block-local exclusive scan of (deg-1) + dinv --
__global__ void k_scan1() {
    __shared__ int warpsums[32];
    int t = threadIdx.x, lane = t & 31, w = t >> 5;
    int i = blockIdx.x * 1024 + t;
    int dg = (i < NN) ? g_deg[i] : 1;
    if (i < NN) g_dinv[i] = rsqrtf((float)dg);
    int v = dg - 1;
    int s = v;
#pragma unroll
    for (int off = 1; off < 32; off <<= 1) {
        int tmp = __shfl_up_sync(0xffffffffu, s, off);
        if (lane >= off) s += tmp;
    }
    if (lane == 31) warpsums[w] = s;
    __syncthreads();
    if (w == 0) {
        int ws = warpsums[lane];
#pragma unroll
        for (int off = 1; off < 32; off <<= 1) {
            int tmp = __shfl_up_sync(0xffffffffu, ws, off);
            if (lane >= off) ws += tmp;
        }
        warpsums[lane] = ws;
    }
    __syncthreads();
    int incl = s + ((w == 0) ? 0 : warpsums[w - 1]);
    if (i < NN) g_off[i] = incl - v;        // block-local exclusive
    if (t == 1023) g_bsum[blockIdx.x] = incl;
}

// ---------------- phase-2: fixup; each block redundantly reduces ALL 98 sums --
#define SB 98
__global__ void k_scan3() {
    __shared__ int spref, stot;
    int t = threadIdx.x, b = blockIdx.x;
    if (t < 32) {
        int v0 = g_bsum[t];                                   // blocks 0..31
        int v1 = g_bsum[t + 32];                              // blocks 32..63
        int v2 = (t + 64 < SB) ? g_bsum[t + 64] : 0;          // blocks 64..95
        int v3 = (t + 96 < SB) ? g_bsum[t + 96] : 0;          // blocks 96..97  (R9 bug: was missing)
        int p = ((t < b) ? v0 : 0) + ((t + 32 < b) ? v1 : 0)
              + ((t + 64 < b) ? v2 : 0) + ((t + 96 < b) ? v3 : 0);
        int q = v0 + v1 + v2 + v3;
#pragma unroll
        for (int off = 16; off; off >>= 1) {
            p += __shfl_down_sync(0xffffffffu, p, off);
            q += __shfl_down_sync(0xffffffffu, q, off);
        }
        if (t == 0) { spref = p; stot = q; }
    }
    __syncthreads();
    int i = b * 1024 + t;
    if (i < NN) {
        int o = g_off[i] + spref;
        g_off[i] = o;
        g_cur[i] = o;
    }
    if (b == SB - 1 && t == 0) g_off[NN] = stot;
}

// ---------------- CSR scatter (blocks [0,SCATB)) + y2 *= dinv (rest) ---------
#define SCATB 6250
#define SCALB 3125          // 3125*256*4 = 3.2M ull = NN*32
__global__ void k_scatter() {
    int b = blockIdx.x, t = threadIdx.x;
    if (b < SCATB) {
        int e = b * 256 + t;
        if (e < EE) {
            int s = g_src32[e], d = g_dst32[e];
            int pos = atomicAdd(&g_cur[d], 1);
            g_srcs[pos] = s * 32;           // prescaled element offset into g_y2
        }
    } else {
        size_t base = (size_t)(b - SCATB) * 1024 + t;
#pragma unroll
        for (int r = 0; r < 4; r++) {
            size_t i = base + (size_t)r * 256;
            if (i < (size_t)NN * 32) {
                float dv = g_dinv[i >> 5];
                g_y2[i] = mul2(g_y2[i], pack2(dv, dv));
            }
        }
    }
}

// ---------------- aggregate + GRU gates: warp per node, 2 edges/iter ----------
__global__ void k_agg() {
    int gw = (blockIdx.x * blockDim.x + threadIdx.x) >> 5;
    int lane = threadIdx.x & 31;
    if (gw >= NN) return;
    int n = gw;
    int half = lane >> 4;               // 0: even edge, 1: odd edge
    int eoff = (lane & 15) * 2;         // feature pair this lane covers
    ull acc0 = 0, acc1 = 0;             // features eoff, eoff+1
    if (half == 0) {
        ulonglong2 sv = *(const ulonglong2*)&g_y2[n * 32 + eoff];   // self term
        acc0 = sv.x; acc1 = sv.y;
    }
    int beg = g_off[n], end = g_off[n + 1];
    int idx = beg;
    for (; idx + 1 < end; idx += 2) {
        int s0 = g_srcs[idx];
        int s1 = g_srcs[idx + 1];
        int base = (half ? s1 : s0) + eoff;
        ulonglong2 v = *(const ulonglong2*)&g_y2[base];
        acc0 = add2(acc0, v.x);
        acc1 = add2(acc1, v.y);
    }
    if (idx < end && half == 0) {
        ulonglong2 v = *(const ulonglong2*)&g_y2[g_srcs[idx] + eoff];
        acc0 = add2(acc0, v.x);
        acc1 = add2(acc1, v.y);
    }
    // combine half-warps: lanes 0-15 gain lanes 16-31's partials
    ull o0 = __shfl_down_sync(0xffffffffu, acc0, 16);
    ull o1 = __shfl_down_sync(0xffffffffu, acc1, 16);
    if (half == 0) {
        acc0 = add2(acc0, o0);
        acc1 = add2(acc1, o1);
        float dn = g_dinv[n];
        ull dpack = pack2(dn, dn);
        acc0 = fma2(acc0, dpack, g_beff2[eoff]);
        acc1 = fma2(acc1, dpack, g_beff2[eoff + 1]);
        float vz0, vh0, vz1, vh1;
        unpack2(acc0, vz0, vh0);
        unpack2(acc1, vz1, vh1);
        float z0 = 1.f / (1.f + __expf(-vz0));
        float z1 = 1.f / (1.f + __expf(-vz1));
        float h0 = tanhf(vh0);
        float h1 = tanhf(vh1);
        float2 res = make_float2((1.f - z0) * h0, (1.f - z1) * h1);
        *(float2*)&g_H[(size_t)n * HID + eoff] = res;
    }
}

// ---------------- edge MLP: 2 edges per thread, f32x2 (R5-proven) -------------
__global__ void k_edge(const float* __restrict__ w1, const float* __restrict__ b1,
                       const float* __restrict__ w2, const float* __restrict__ b2,
                       float* __restrict__ out) {
    __shared__ ull sw1[HID * 16];       // row j: 16 packed (w1[2p][j], w1[2p+1][j])
    __shared__ float sb1[HID], sw2[HID];
    __shared__ float sb2;
    int tid = threadIdx.x;
    for (int i = tid; i < HID * 16; i += blockDim.x) {
        int j = i >> 4, p = i & 15;
        sw1[j * 16 + p] = pack2(w1[(2 * p) * HID + j], w1[(2 * p + 1) * HID + j]);
    }
    if (tid < HID) { sb1[tid] = b1[tid]; sw2[tid] = w2[tid]; }
    if (tid == 0) sb2 = b2[0];
    __syncthreads();
    int e0 = blockIdx.x * 512 + tid;
    int e1 = e0 + 256;
    bool v0 = (e0 < EE), v1 = (e1 < EE);

    ull emb0[16], emb1[16];
    if (v0) {
        const float4* Hs = (const float4*)(g_H + (size_t)g_src32[e0] * HID);
        const float4* Hd = (const float4*)(g_H + (size_t)g_dst32[e0] * HID);
#pragma unroll
        for (int i = 0; i < 8; i++) {
            float4 a = Hs[i], b = Hd[i];
            const ull* ap = (const ull*)&a; const ull* bp = (const ull*)&b;
            emb0[2 * i]     = mul2(ap[0], bp[0]);
            emb0[2 * i + 1] = mul2(ap[1], bp[1]);
        }
    }
    if (v1) {
        const float4* Hs = (const float4*)(g_H + (size_t)g_src32[e1] * HID);
        const float4* Hd = (const float4*)(g_H + (size_t)g_dst32[e1] * HID);
#pragma unroll
        for (int i = 0; i < 8; i++) {
            float4 a = Hs[i], b = Hd[i];
            const ull* ap = (const ull*)&a; const ull* bp = (const ull*)&b;
            emb1[2 * i]     = mul2(ap[0], bp[0]);
            emb1[2 * i + 1] = mul2(ap[1], bp[1]);
        }
    }
    if (!v0) return;

    float logit0 = sb2, logit1 = sb2;
#pragma unroll 2
    for (int j = 0; j < HID; j++) {
        ull acc0 = 0, acc1 = 0;
        const ull* wr = &sw1[j * 16];
#pragma unroll
        for (int p = 0; p < 16; p++) {
            ull w = wr[p];
            acc0 = fma2(emb0[p], w, acc0);
            acc1 = fma2(emb1[p], w, acc1);
        }
        float lo, hi, l1, h1v;
        unpack2(acc0, lo, hi);
        unpack2(acc1, l1, h1v);
        float h0 = fmaxf(lo + hi + sb1[j], 0.f);
        float h1 = fmaxf(l1 + h1v + sb1[j], 0.f);
        logit0 = fmaf(h0, sw2[j], logit0);
        logit1 = fmaf(h1, sw2[j], logit1);
    }
    out[e0] = 1.f / (1.f + __expf(-logit0));
    if (v1) out[e1] = 1.f / (1.f + __expf(-logit1));
}

// ---------------- launch ------------------------------------------------------
extern "C" void kernel_launch(void* const* d_in, const int* in_sizes, int n_in,
                              void* d_out, int out_size) {
    const float* x   = (const float*)d_in[0];
    const void*  ei  = d_in[1];
    const float* Wz  = (const float*)d_in[2];
    const float* bz  = (const float*)d_in[3];
    const float* Wh  = (const float*)d_in[6];
    const float* bh  = (const float*)d_in[7];
    const float* Lzw = (const float*)d_in[8];
    const float* Lzb = (const float*)d_in[9];
    const float* Lhw = (const float*)d_in[12];
    const float* Lhb = (const float*)d_in[13];
    const float* w1  = (const float*)d_in[14];
    const float* b1  = (const float*)d_in[15];
    const float* w2  = (const float*)d_in[16];
    const float* b2  = (const float*)d_in[17];
    float* out = (float*)d_out;

    k_prep<<<424, 256>>>(ei, Wz, Wh, Lzw, Lhw, bz, bh, Lzb, Lhb);
    k_main1<<<GEMMB + DEGB, 256>>>(x, ei);
    k_scan1<<<98, 1024>>>();
    k_scan3<<<SB, 1024>>>();
    k_scatter<<<SCATB + SCALB, 256>>>();
    k_agg<<<(NN * 32 + 255) / 256, 256>>>();
    k_edge<<<(EE + 511) / 512, 256>>>(w1, b1, w2, b2, out);
}

// round 11
// speedup vs baseline: 1.0269x; 1.0269x over previous
#include <cuda_runtime.h>
#include <math.h>

#define NN 100000
#define EE 1600000
#define DD 128
#define HID 32

typedef unsigned long long ull;

// ---------------- scratch (device globals) ------------------------------------
__device__ int   g_is64;
__device__ int   g_deg[NN];
__device__ float g_dinv[NN];
__device__ int   g_off[NN + 1];
__device__ int   g_cur[NN];
__device__ int   g_src32[EE];
__device__ int   g_dst32[EE];
__device__ int   g_srcs[EE];                // CSR: prescaled src element offsets (s*32)
__device__ ulonglong2 g_y2v[(size_t)NN * 16];   // (z,h) packed pairs, pre-scaled by dinv
#define g_y2 ((ull*)g_y2v)
__device__ float g_H[(size_t)NN * HID];
__device__ float g_WT[64 * DD];             // WeffT[j][k], j: 0..31=z, 32..63=h
__device__ ull   g_beff2[32];               // packed (bz_eff, bh_eff)
__device__ int   g_bsum[128];

// ---------------- f32x2 helpers -----------------------------------------------
__device__ __forceinline__ ull pack2(float a, float b) {
    ull r; asm("mov.b64 %0, {%1, %2};" : "=l"(r) : "f"(a), "f"(b)); return r;
}
__device__ __forceinline__ void unpack2(ull v, float& a, float& b) {
    asm("mov.b64 {%0, %1}, %2;" : "=f"(a), "=f"(b) : "l"(v));
}
__device__ __forceinline__ ull fma2(ull a, ull b, ull c) {
    ull d; asm("fma.rn.f32x2 %0, %1, %2, %3;" : "=l"(d) : "l"(a), "l"(b), "l"(c)); return d;
}
__device__ __forceinline__ ull mul2(ull a, ull b) {
    ull d; asm("mul.rn.f32x2 %0, %1, %2;" : "=l"(d) : "l"(a), "l"(b)); return d;
}
__device__ __forceinline__ ull add2(ull a, ull b) {
    ull d; asm("add.rn.f32x2 %0, %1, %2;" : "=l"(d) : "l"(a), "l"(b)); return d;
}

__device__ __forceinline__ int edge_at(const void* ei, int is64, long long idx) {
    return is64 ? (int)((const long long*)ei)[idx] : ((const int*)ei)[idx];
}

// ---------------- prep: detect + deg init + Weff^T + beff ---------------------
__global__ void k_prep(const void* ei,
                       const float* Wz, const float* Wh,
                       const float* Lzw, const float* Lhw,
                       const float* bz, const float* bh,
                       const float* Lzb, const float* Lhb) {
    int b = blockIdx.x, t = threadIdx.x;
    if (b < 391) {
        int i = b * 256 + t;
        if (i < NN) g_deg[i] = 1;           // self loop
    } else if (b == 391) {
        __shared__ int s;
        if (t == 0) s = 1;
        __syncthreads();
        const long long* p = (const long long*)ei;
        for (int i = t; i < 4096; i += 256)
            if ((p[i] >> 32) != 0) s = 0;
        __syncthreads();
        if (t == 0) g_is64 = s;
    } else {
        int idx = (b - 392) * 256 + t;      // [0, 8192)
        int k = idx >> 6, j = idx & 63;
        float acc = 0.f;
        if (j < HID) {
            for (int m = 0; m < HID; m++) acc = fmaf(Wz[k * HID + m], Lzw[m * HID + j], acc);
        } else {
            int jj = j - HID;
            for (int m = 0; m < HID; m++) acc = fmaf(Wh[k * HID + m], Lhw[m * HID + jj], acc);
        }
        g_WT[j * DD + k] = acc;             // transposed store
        if (b == 392 && t < 32) {
            float az = Lzb[t], ah = Lhb[t];
            for (int m = 0; m < HID; m++) {
                az = fmaf(bz[m], Lzw[m * HID + t], az);
                ah = fmaf(bh[m], Lhw[m * HID + t], ah);
            }
            g_beff2[t] = pack2(az, ah);
        }
    }
}

// ---------------- edge conversion + degree count (now FIRST) ------------------
__global__ void k_deg(const void* __restrict__ ei) {
    int is64 = g_is64;
    int e = blockIdx.x * 256 + threadIdx.x;
    if (e < EE) {
        int s = edge_at(ei, is64, e);
        int d = edge_at(ei, is64, (long long)EE + e);
        g_src32[e] = s;
        g_dst32[e] = d;
        atomicAdd(&g_deg[d], 1);
    }
}

// ---------------- phase-1 scan: block-local exclusive scan of (deg-1) + dinv --
__global__ void k_scan1() {
    __shared__ int warpsums[32];
    int t = threadIdx.x, lane = t & 31, w = t >> 5;
    int i = blockIdx.x * 1024 + t;
    int dg = (i < NN) ? g_deg[i] : 1;
    if (i < NN) g_dinv[i] = rsqrtf((float)dg);
    int v = dg - 1;
    int s = v;
#pragma unroll
    for (int off = 1; off < 32; off <<= 1) {
        int tmp = __shfl_up_sync(0xffffffffu, s, off);
        if (lane >= off) s += tmp;
    }
    if (lane == 31) warpsums[w] = s;
    __syncthreads();
    if (w == 0) {
        int ws = warpsums[lane];
#pragma unroll
        for (int off = 1; off < 32; off <<= 1) {
            int tmp = __shfl_up_sync(0xffffffffu, ws, off);
            if (lane >= off) ws += tmp;
        }
        warpsums[lane] = ws;
    }
    __syncthreads();
    int incl = s + ((w == 0) ? 0 : warpsums[w - 1]);
    if (i < NN) g_off[i] = incl - v;        // block-local exclusive
    if (t == 1023) g_bsum[blockIdx.x] = incl;
}

// ---------------- phase-2: fixup; each block redundantly reduces ALL 98 sums --
#define SB 98
__global__ void k_scan3() {
    __shared__ int spref, stot;
    int t = threadIdx.x, b = blockIdx.x;
    if (t < 32) {
        int v0 = g_bsum[t];
        int v1 = g_bsum[t + 32];
        int v2 = (t + 64 < SB) ? g_bsum[t + 64] : 0;
        int v3 = (t + 96 < SB) ? g_bsum[t + 96] : 0;
        int p = ((t < b) ? v0 : 0) + ((t + 32 < b) ? v1 : 0)
              + ((t + 64 < b) ? v2 : 0) + ((t + 96 < b) ? v3 : 0);
        int q = v0 + v1 + v2 + v3;
#pragma unroll
        for (int off = 16; off; off >>= 1) {
            p += __shfl_down_sync(0xffffffffu, p, off);
            q += __shfl_down_sync(0xffffffffu, q, off);
        }
        if (t == 0) { spref = p; stot = q; }
    }
    __syncthreads();
    int i = b * 1024 + t;
    if (i < NN) {
        int o = g_off[i] + spref;
        g_off[i] = o;
        g_cur[i] = o;
    }
    if (b == SB - 1 && t == 0) g_off[NN] = stot;
}

// ---------------- fused: GEMM×dinv (blocks [0,GEMMB)) + CSR scatter -----------
#define GEMMB 3125
#define SCATB 6250
__global__ void k_gemm_scat(const float* __restrict__ x) {
    __shared__ float sWT[64 * 130];         // padded rows: stride 130 floats
    int t = threadIdx.x;
    if (blockIdx.x < GEMMB) {
        for (int i = t; i < 64 * 128; i += 256) {
            int j = i >> 7, k = i & 127;
            sWT[j * 130 + k] = g_WT[i];
        }
        __syncthreads();
        int warp = t >> 5, lane = t & 31;
        int n0 = (blockIdx.x * 8 + warp) * 4;       // 4 nodes per warp
        if (n0 >= NN) return;
        const float4* x4 = (const float4*)x;
        ull az[4] = {0, 0, 0, 0}, ah[4] = {0, 0, 0, 0};
        const ull* wzr = (const ull*)&sWT[lane * 130];
        const ull* whr = (const ull*)&sWT[(lane + 32) * 130];
#pragma unroll 4
        for (int k4 = 0; k4 < 32; k4++) {
            float4 a0 = x4[(size_t)(n0 + 0) * 32 + k4];
            float4 a1 = x4[(size_t)(n0 + 1) * 32 + k4];
            float4 a2 = x4[(size_t)(n0 + 2) * 32 + k4];
            float4 a3 = x4[(size_t)(n0 + 3) * 32 + k4];
            ull wz0 = wzr[k4 * 2], wz1 = wzr[k4 * 2 + 1];
            ull wh0 = whr[k4 * 2], wh1 = whr[k4 * 2 + 1];
            const ull* p0 = (const ull*)&a0; const ull* p1 = (const ull*)&a1;
            const ull* p2 = (const ull*)&a2; const ull* p3 = (const ull*)&a3;
            az[0] = fma2(p0[0], wz0, az[0]); az[0] = fma2(p0[1], wz1, az[0]);
            ah[0] = fma2(p0[0], wh0, ah[0]); ah[0] = fma2(p0[1], wh1, ah[0]);
            az[1] = fma2(p1[0], wz0, az[1]); az[1] = fma2(p1[1], wz1, az[1]);
            ah[1] = fma2(p1[0], wh0, ah[1]); ah[1] = fma2(p1[1], wh1, ah[1]);
            az[2] = fma2(p2[0], wz0, az[2]); az[2] = fma2(p2[1], wz1, az[2]);
            ah[2] = fma2(p2[0], wh0, ah[2]); ah[2] = fma2(p2[1], wh1, ah[2]);
            az[3] = fma2(p3[0], wz0, az[3]); az[3] = fma2(p3[1], wz1, az[3]);
            ah[3] = fma2(p3[0], wh0, ah[3]); ah[3] = fma2(p3[1], wh1, ah[3]);
        }
#pragma unroll
        for (int i = 0; i < 4; i++) {
            float dn = g_dinv[n0 + i];                  // fold dinv into epilogue
            float zl, zh, hl, hh;
            unpack2(az[i], zl, zh);
            unpack2(ah[i], hl, hh);
            g_y2[(size_t)(n0 + i) * 32 + lane] = pack2((zl + zh) * dn, (hl + hh) * dn);
        }
    } else {
        int e = (blockIdx.x - GEMMB) * 256 + t;
        if (e < EE) {
            int s = g_src32[e], d = g_dst32[e];
            int pos = atomicAdd(&g_cur[d], 1);
            g_srcs[pos] = s * 32;           // prescaled element offset into g_y2
        }
    }
}

// ---------------- aggregate + GRU gates: warp per node (R8-proven) ------------
__global__ void k_agg() {
    int warp = (blockIdx.x * blockDim.x + threadIdx.x) >> 5;
    int lane = threadIdx.x & 31;
    if (warp >= NN) return;
    int n = warp;
    ull a0 = g_y2[(size_t)n * 32 + lane];    // self term (ys[n], pre-scaled)
    ull a1 = 0;
    int beg = g_off[n], end = g_off[n + 1];
    int idx = beg;
    for (; idx + 1 < end; idx += 2) {
        int o0 = g_srcs[idx] + lane;
        int o1 = g_srcs[idx + 1] + lane;
        a0 = add2(a0, g_y2[o0]);
        a1 = add2(a1, g_y2[o1]);
    }
    if (idx < end) a0 = add2(a0, g_y2[g_srcs[idx] + lane]);
    float dn = g_dinv[n];
    ull acc = fma2(add2(a0, a1), pack2(dn, dn), g_beff2[lane]);
    float vz, vh;
    unpack2(acc, vz, vh);
    float z  = 1.f / (1.f + __expf(-vz));
    float ht = tanhf(vh);
    g_H[(size_t)n * HID + lane] = (1.f - z) * ht;
}

// ---------------- edge MLP: 2 edges per thread, f32x2 (R8-proven) -------------
__global__ void k_edge(const float* __restrict__ w1, const float* __restrict__ b1,
                       const float* __restrict__ w2, const float* __restrict__ b2,
                       float* __restrict__ out) {
    __shared__ ull sw1[HID * 16];       // row j: 16 packed (w1[2p][j], w1[2p+1][j])
    __shared__ float sb1[HID], sw2[HID];
    __shared__ float sb2;
    int tid = threadIdx.x;
    for (int i = tid; i < HID * 16; i += blockDim.x) {
        int j = i >> 4, p = i & 15;
        sw1[j * 16 + p] = pack2(w1[(2 * p) * HID + j], w1[(2 * p + 1) * HID + j]);
    }
    if (tid < HID) { sb1[tid] = b1[tid]; sw2[tid] = w2[tid]; }
    if (tid == 0) sb2 = b2[0];
    __syncthreads();
    int e0 = blockIdx.x * 512 + tid;
    int e1 = e0 + 256;
    bool v0 = (e0 < EE), v1 = (e1 < EE);

    ull emb0[16], emb1[16];
    if (v0) {
        const float4* Hs = (const float4*)(g_H + (size_t)g_src32[e0] * HID);
        const float4* Hd = (const float4*)(g_H + (size_t)g_dst32[e0] * HID);
#pragma unroll
        for (int i = 0; i < 8; i++) {
            float4 a = Hs[i], b = Hd[i];
            const ull* ap = (const ull*)&a; const ull* bp = (const ull*)&b;
            emb0[2 * i]     = mul2(ap[0], bp[0]);
            emb0[2 * i + 1] = mul2(ap[1], bp[1]);
        }
    }
    if (v1) {
        const float4* Hs = (const float4*)(g_H + (size_t)g_src32[e1] * HID);
        const float4* Hd = (const float4*)(g_H + (size_t)g_dst32[e1] * HID);
#pragma unroll
        for (int i = 0; i < 8; i++) {
            float4 a = Hs[i], b = Hd[i];
            const ull* ap = (const ull*)&a; const ull* bp = (const ull*)&b;
            emb1[2 * i]     = mul2(ap[0], bp[0]);
            emb1[2 * i + 1] = mul2(ap[1], bp[1]);
        }
    }
    if (!v0) return;

    float logit0 = sb2, logit1 = sb2;
#pragma unroll 2
    for (int j = 0; j < HID; j++) {
        ull acc0 = 0, acc1 = 0;
        const ull* wr = &sw1[j * 16];
#pragma unroll
        for (int p = 0; p < 16; p++) {
            ull w = wr[p];
            acc0 = fma2(emb0[p], w, acc0);
            acc1 = fma2(emb1[p], w, acc1);
        }
        float lo, hi, l1, h1v;
        unpack2(acc0, lo, hi);
        unpack2(acc1, l1, h1v);
        float h0 = fmaxf(lo + hi + sb1[j], 0.f);
        float h1 = fmaxf(l1 + h1v + sb1[j], 0.f);
        logit0 = fmaf(h0, sw2[j], logit0);
        logit1 = fmaf(h1, sw2[j], logit1);
    }
    out[e0] = 1.f / (1.f + __expf(-logit0));
    if (v1) out[e1] = 1.f / (1.f + __expf(-logit1));
}

// ---------------- launch ------------------------------------------------------
extern "C" void kernel_launch(void* const* d_in, const int* in_sizes, int n_in,
                              void* d_out, int out_size) {
    const float* x   = (const float*)d_in[0];
    const void*  ei  = d_in[1];
    const float* Wz  = (const float*)d_in[2];
    const float* bz  = (const float*)d_in[3];
    const float* Wh  = (const float*)d_in[6];
    const float* bh  = (const float*)d_in[7];
    const float* Lzw = (const float*)d_in[8];
    const float* Lzb = (const float*)d_in[9];
    const float* Lhw = (const float*)d_in[12];
    const float* Lhb = (const float*)d_in[13];
    const float* w1  = (const float*)d_in[14];
    const float* b1  = (const float*)d_in[15];
    const float* w2  = (const float*)d_in[16];
    const float* b2  = (const float*)d_in[17];
    float* out = (float*)d_out;

    k_prep<<<424, 256>>>(ei, Wz, Wh, Lzw, Lhw, bz, bh, Lzb, Lhb);
    k_deg<<<6250, 256>>>(ei);
    k_scan1<<<98, 1024>>>();
    k_scan3<<<SB, 1024>>>();
    k_gemm_scat<<<GEMMB + SCATB, 256>>>(x);
    k_agg<<<(NN * 32 + 255) / 256, 256>>>();
    k_edge<<<(EE + 511) / 512, 256>>>(w1, b1, w2, b2, out);
}

// round 12
// speedup vs baseline: 1.0336x; 1.0065x over previous
#include <cuda_runtime.h>
#include <cuda_fp16.h>
#include <math.h>

#define NN 100000
#define EE 1600000
#define DD 128
#define HID 32

typedef unsigned long long ull;

// ---------------- scratch (device globals) ------------------------------------
__device__ int      g_is64;
__device__ int      g_deg[NN];
__device__ float    g_dinv[NN];
__device__ int      g_off[NN + 1];
__device__ int      g_cur[NN];
__device__ int      g_src32[EE];
__device__ int      g_dst32[EE];
__device__ int      g_srcs[EE];             // CSR: prescaled src element offsets (s*32)
__device__ unsigned g_y2h[(size_t)NN * 32]; // half2(z,h) per (node,feature); pre-scaled by dinv
__device__ float    g_H[(size_t)NN * HID];
__device__ float    g_WT[64 * DD];          // WeffT[j][k], j: 0..31=z, 32..63=h
__device__ ull      g_beff2[32];            // packed (bz_eff, bh_eff) fp32
__device__ int      g_bsum[128];

// ---------------- f32x2 helpers -----------------------------------------------
__device__ __forceinline__ ull pack2(float a, float b) {
    ull r; asm("mov.b64 %0, {%1, %2};" : "=l"(r) : "f"(a), "f"(b)); return r;
}
__device__ __forceinline__ void unpack2(ull v, float& a, float& b) {
    asm("mov.b64 {%0, %1}, %2;" : "=f"(a), "=f"(b) : "l"(v));
}
__device__ __forceinline__ ull fma2(ull a, ull b, ull c) {
    ull d; asm("fma.rn.f32x2 %0, %1, %2, %3;" : "=l"(d) : "l"(a), "l"(b), "l"(c)); return d;
}
__device__ __forceinline__ ull mul2(ull a, ull b) {
    ull d; asm("mul.rn.f32x2 %0, %1, %2;" : "=l"(d) : "l"(a), "l"(b)); return d;
}

__device__ __forceinline__ int edge_at(const void* ei, int is64, long long idx) {
    return is64 ? (int)((const long long*)ei)[idx] : ((const int*)ei)[idx];
}

// ---------------- prep: detect + deg init + Weff^T + beff ---------------------
__global__ void k_prep(const void* ei,
                       const float* Wz, const float* Wh,
                       const float* Lzw, const float* Lhw,
                       const float* bz, const float* bh,
                       const float* Lzb, const float* Lhb) {
    int b = blockIdx.x, t = threadIdx.x;
    if (b < 391) {
        int i = b * 256 + t;
        if (i < NN) g_deg[i] = 1;           // self loop
    } else if (b == 391) {
        __shared__ int s;
        if (t == 0) s = 1;
        __syncthreads();
        const long long* p = (const long long*)ei;
        for (int i = t; i < 4096; i += 256)
            if ((p[i] >> 32) != 0) s = 0;
        __syncthreads();
        if (t == 0) g_is64 = s;
    } else {
        int idx = (b - 392) * 256 + t;      // [0, 8192)
        int k = idx >> 6, j = idx & 63;
        float acc = 0.f;
        if (j < HID) {
            for (int m = 0; m < HID; m++) acc = fmaf(Wz[k * HID + m], Lzw[m * HID + j], acc);
        } else {
            int jj = j - HID;
            for (int m = 0; m < HID; m++) acc = fmaf(Wh[k * HID + m], Lhw[m * HID + jj], acc);
        }
        g_WT[j * DD + k] = acc;             // transposed store
        if (b == 392 && t < 32) {
            float az = Lzb[t], ah = Lhb[t];
            for (int m = 0; m < HID; m++) {
                az = fmaf(bz[m], Lzw[m * HID + t], az);
                ah = fmaf(bh[m], Lhw[m * HID + t], ah);
            }
            g_beff2[t] = pack2(az, ah);
        }
    }
}

// ---------------- edge conversion + degree count ------------------------------
__global__ void k_deg(const void* __restrict__ ei) {
    int is64 = g_is64;
    int e = blockIdx.x * 256 + threadIdx.x;
    if (e < EE) {
        int s = edge_at(ei, is64, e);
        int d = edge_at(ei, is64, (long long)EE + e);
        g_src32[e] = s;
        g_dst32[e] = d;
        atomicAdd(&g_deg[d], 1);
    }
}

// ---------------- phase-1 scan: block-local exclusive scan of (deg-1) + dinv --
__global__ void k_scan1() {
    __shared__ int warpsums[32];
    int t = threadIdx.x, lane = t & 31, w = t >> 5;
    int i = blockIdx.x * 1024 + t;
    int dg = (i < NN) ? g_deg[i] : 1;
    if (i < NN) g_dinv[i] = rsqrtf((float)dg);
    int v = dg - 1;
    int s = v;
#pragma unroll
    for (int off = 1; off < 32; off <<= 1) {
        int tmp = __shfl_up_sync(0xffffffffu, s, off);
        if (lane >= off) s += tmp;
    }
    if (lane == 31) warpsums[w] = s;
    __syncthreads();
    if (w == 0) {
        int ws = warpsums[lane];
#pragma unroll
        for (int off = 1; off < 32; off <<= 1) {
            int tmp = __shfl_up_sync(0xffffffffu, ws, off);
            if (lane >= off) ws += tmp;
        }
        warpsums[lane] = ws;
    }
    __syncthreads();
    int incl = s + ((w == 0) ? 0 : warpsums[w - 1]);
    if (i < NN) g_off[i] = incl - v;        // block-local exclusive
    if (t == 1023) g_bsum[blockIdx.x] = incl;
}

// ---------------- phase-2: fixup; each block redundantly reduces ALL 98 sums --
#define SB 98
__global__ void k_scan3() {
    __shared__ int spref, stot;
    int t = threadIdx.x, b = blockIdx.x;
    if (t < 32) {
        int v0 = g_bsum[t];
        int v1 = g_bsum[t + 32];
        int v2 = (t + 64 < SB) ? g_bsum[t + 64] : 0;
        int v3 = (t + 96 < SB) ? g_bsum[t + 96] : 0;
        int p = ((t < b) ? v0 : 0) + ((t + 32 < b) ? v1 : 0)
              + ((t + 64 < b) ? v2 : 0) + ((t + 96 < b) ? v3 : 0);
        int q = v0 + v1 + v2 + v3;
#pragma unroll
        for (int off = 16; off; off >>= 1) {
            p += __shfl_down_sync(0xffffffffu, p, off);
            q += __shfl_down_sync(0xffffffffu, q, off);
        }
        if (t == 0) { spref = p; stot = q; }
    }
    __syncthreads();
    int i = b * 1024 + t;
    if (i < NN) {
        int o = g_off[i] + spref;
        g_off[i] = o;
        g_cur[i] = o;
    }
    if (b == SB - 1 && t == 0) g_off[NN] = stot;
}

// ---------------- fused: GEMM×dinv→fp16 (blocks [0,GEMMB)) + CSR scatter ------
#define GEMMB 3125
#define SCATB 6250
__global__ void k_gemm_scat(const float* __restrict__ x) {
    __shared__ float sWT[64 * 130];         // padded rows: stride 130 floats
    int t = threadIdx.x;
    if (blockIdx.x < GEMMB) {
        for (int i = t; i < 64 * 128; i += 256) {
            int j = i >> 7, k = i & 127;
            sWT[j * 130 + k] = g_WT[i];
        }
        __syncthreads();
        int warp = t >> 5, lane = t & 31;
        int n0 = (blockIdx.x * 8 + warp) * 4;       // 4 nodes per warp
        if (n0 >= NN) return;
        const float4* x4 = (const float4*)x;
        ull az[4] = {0, 0, 0, 0}, ah[4] = {0, 0, 0, 0};
        const ull* wzr = (const ull*)&sWT[lane * 130];
        const ull* whr = (const ull*)&sWT[(lane + 32) * 130];
#pragma unroll 4
        for (int k4 = 0; k4 < 32; k4++) {
            float4 a0 = x4[(size_t)(n0 + 0) * 32 + k4];
            float4 a1 = x4[(size_t)(n0 + 1) * 32 + k4];
            float4 a2 = x4[(size_t)(n0 + 2) * 32 + k4];
            float4 a3 = x4[(size_t)(n0 + 3) * 32 + k4];
            ull wz0 = wzr[k4 * 2], wz1 = wzr[k4 * 2 + 1];
            ull wh0 = whr[k4 * 2], wh1 = whr[k4 * 2 + 1];
            const ull* p0 = (const ull*)&a0; const ull* p1 = (const ull*)&a1;
            const ull* p2 = (const ull*)&a2; const ull* p3 = (const ull*)&a3;
            az[0] = fma2(p0[0], wz0, az[0]); az[0] = fma2(p0[1], wz1, az[0]);
            ah[0] = fma2(p0[0], wh0, ah[0]); ah[0] = fma2(p0[1], wh1, ah[0]);
            az[1] = fma2(p1[0], wz0, az[1]); az[1] = fma2(p1[1], wz1, az[1]);
            ah[1] = fma2(p1[0], wh0, ah[1]); ah[1] = fma2(p1[1], wh1, ah[1]);
            az[2] = fma2(p2[0], wz0, az[2]); az[2] = fma2(p2[1], wz1, az[2]);
            ah[2] = fma2(p2[0], wh0, ah[2]); ah[2] = fma2(p2[1], wh1, ah[2]);
            az[3] = fma2(p3[0], wz0, az[3]); az[3] = fma2(p3[1], wz1, az[3]);
            ah[3] = fma2(p3[0], wh0, ah[3]); ah[3] = fma2(p3[1], wh1, ah[3]);
        }
#pragma unroll
        for (int i = 0; i < 4; i++) {
            float dn = g_dinv[n0 + i];
            float zl, zh, hl, hh;
            unpack2(az[i], zl, zh);
            unpack2(ah[i], hl, hh);
            __half2 hv = __floats2half2_rn((zl + zh) * dn, (hl + hh) * dn);
            g_y2h[(size_t)(n0 + i) * 32 + lane] = *(unsigned*)&hv;
        }
    } else {
        int e = (blockIdx.x - GEMMB) * 256 + t;
        if (e < EE) {
            int s = g_src32[e], d = g_dst32[e];
            int pos = atomicAdd(&g_cur[d], 1);
            g_srcs[pos] = s * 32;           // prescaled element offset into g_y2h
        }
    }
}

// ---------------- aggregate (fp16 gathers, fp32 accum) + GRU gates ------------
__global__ void k_agg() {
    int warp = (blockIdx.x * blockDim.x + threadIdx.x) >> 5;
    int lane = threadIdx.x & 31;
    if (warp >= NN) return;
    int n = warp;
    unsigned sv = g_y2h[(size_t)n * 32 + lane];     // self term
    float2 f = __half22float2(*(__half2*)&sv);
    float az0 = f.x, ah0 = f.y, az1 = 0.f, ah1 = 0.f;
    int beg = g_off[n], end = g_off[n + 1];
    int idx = beg;
    for (; idx + 1 < end; idx += 2) {
        unsigned v0 = g_y2h[g_srcs[idx] + lane];
        unsigned v1 = g_y2h[g_srcs[idx + 1] + lane];
        float2 f0 = __half22float2(*(__half2*)&v0);
        float2 f1 = __half22float2(*(__half2*)&v1);
        az0 += f0.x; ah0 += f0.y;
        az1 += f1.x; ah1 += f1.y;
    }
    if (idx < end) {
        unsigned v0 = g_y2h[g_srcs[idx] + lane];
        float2 f0 = __half22float2(*(__half2*)&v0);
        az0 += f0.x; ah0 += f0.y;
    }
    float dn = g_dinv[n];
    float bz, bh;
    unpack2(g_beff2[lane], bz, bh);
    float vz = (az0 + az1) * dn + bz;
    float vh = (ah0 + ah1) * dn + bh;
    float z  = 1.f / (1.f + __expf(-vz));
    float ht = tanhf(vh);
    g_H[(size_t)n * HID + lane] = (1.f - z) * ht;
}

// ---------------- edge MLP: 2 edges per thread, f32x2 (R8-proven) -------------
__global__ void k_edge(const float* __restrict__ w1, const float* __restrict__ b1,
                       const float* __restrict__ w2, const float* __restrict__ b2,
                       float* __restrict__ out) {
    __shared__ ull sw1[HID * 16];       // row j: 16 packed (w1[2p][j], w1[2p+1][j])
    __shared__ float sb1[HID], sw2[HID];
    __shared__ float sb2;
    int tid = threadIdx.x;
    for (int i = tid; i < HID * 16; i += blockDim.x) {
        int j = i >> 4, p = i & 15;
        sw1[j * 16 + p] = pack2(w1[(2 * p) * HID + j], w1[(2 * p + 1) * HID + j]);
    }
    if (tid < HID) { sb1[tid] = b1[tid]; sw2[tid] = w2[tid]; }
    if (tid == 0) sb2 = b2[0];
    __syncthreads();
    int e0 = blockIdx.x * 512 + tid;
    int e1 = e0 + 256;
    bool v0 = (e0 < EE), v1 = (e1 < EE);

    ull emb0[16], emb1[16];
    if (v0) {
        const float4* Hs = (const float4*)(g_H + (size_t)g_src32[e0] * HID);
        const float4* Hd = (const float4*)(g_H + (size_t)g_dst32[e0] * HID);
#pragma unroll
        for (int i = 0; i < 8; i++) {
            float4 a = Hs[i], b = Hd[i];
            const ull* ap = (const ull*)&a; const ull* bp = (const ull*)&b;
            emb0[2 * i]     = mul2(ap[0], bp[0]);
            emb0[2 * i + 1] = mul2(ap[1], bp[1]);
        }
    }
    if (v1) {
        const float4* Hs = (const float4*)(g_H + (size_t)g_src32[e1] * HID);
        const float4* Hd = (const float4*)(g_H + (size_t)g_dst32[e1] * HID);
#pragma unroll
        for (int i = 0; i < 8; i++) {
            float4 a = Hs[i], b = Hd[i];
            const ull* ap = (const ull*)&a; const ull* bp = (const ull*)&b;
            emb1[2 * i]     = mul2(ap[0], bp[0]);
            emb1[2 * i + 1] = mul2(ap[1], bp[1]);
        }
    }
    if (!v0) return;

    float logit0 = sb2, logit1 = sb2;
#pragma unroll 2
    for (int j = 0; j < HID; j++) {
        ull acc0 = 0, acc1 = 0;
        const ull* wr = &sw1[j * 16];
#pragma unroll
        for (int p = 0; p < 16; p++) {
            ull w = wr[p];
            acc0 = fma2(emb0[p], w, acc0);
            acc1 = fma2(emb1[p], w, acc1);
        }
        float lo, hi, l1, h1v;
        unpack2(acc0, lo, hi);
        unpack2(acc1, l1, h1v);
        float h0 = fmaxf(lo + hi + sb1[j], 0.f);
        float h1 = fmaxf(l1 + h1v + sb1[j], 0.f);
        logit0 = fmaf(h0, sw2[j], logit0);
        logit1 = fmaf(h1, sw2[j], logit1);
    }
    out[e0] = 1.f / (1.f + __expf(-logit0));
    if (v1) out[e1] = 1.f / (1.f + __expf(-logit1));
}

// ---------------- launch ------------------------------------------------------
extern "C" void kernel_launch(void* const* d_in, const int* in_sizes, int n_in,
                              void* d_out, int out_size) {
    const float* x   = (const float*)d_in[0];
    const void*  ei  = d_in[1];
    const float* Wz  = (const float*)d_in[2];
    const float* bz  = (const float*)d_in[3];
    const float* Wh  = (const float*)d_in[6];
    const float* bh  = (const float*)d_in[7];
    const float* Lzw = (const float*)d_in[8];
    const float* Lzb = (const float*)d_in[9];
    const float* Lhw = (const float*)d_in[12];
    const float* Lhb = (const float*)d_in[13];
    const float* w1  = (const float*)d_in[14];
    const float* b1  = (const float*)d_in[15];
    const float* w2  = (const float*)d_in[16];
    const float* b2  = (const float*)d_in[17];
    float* out = (float*)d_out;

    k_prep<<<424, 256>>>(ei, Wz, Wh, Lzw, Lhw, bz, bh, Lzb, Lhb);
    k_deg<<<6250, 256>>>(ei);
    k_scan1<<<98, 1024>>>();
    k_scan3<<<SB, 1024>>>();
    k_gemm_scat<<<GEMMB + SCATB, 256>>>(x);
    k_agg<<<(NN * 32 + 255) / 256, 256>>>();
    k_edge<<<(EE + 511) / 512, 256>>>(w1, b1, w2, b2, out);
}

// round 14
// speedup vs baseline: 1.2881x; 1.2463x over previous
#include <cuda_runtime.h>
#include <cuda_fp16.h>
#include <math.h>

#define NN 100000
#define EE 1600000
#define DD 128
#define HID 32

typedef unsigned long long ull;

// ---------------- scratch (device globals) ------------------------------------
__device__ int      g_is64;
__device__ int      g_deg[NN];
__device__ float    g_dinv[NN];
__device__ int      g_off[NN + 1];
__device__ int      g_cur[NN];
__device__ int      g_src32[EE];
__device__ int      g_dst32[EE];
__device__ int      g_srcs[EE];             // CSR: prescaled src element offsets (s*32)
__device__ unsigned g_y2h[(size_t)NN * 32]; // half2(z,h) per (node,feature); pre-scaled by dinv
__device__ __half   g_Hh[(size_t)NN * 32];  // H in fp16, 64B rows
__device__ float    g_WT[64 * DD];          // WeffT[j][k], j: 0..31=z, 32..63=h
__device__ ull      g_beff2[32];            // packed (bz_eff, bh_eff) fp32
__device__ int      g_bsum[128];

// ---------------- f32x2 helpers -----------------------------------------------
__device__ __forceinline__ ull pack2(float a, float b) {
    ull r; asm("mov.b64 %0, {%1, %2};" : "=l"(r) : "f"(a), "f"(b)); return r;
}
__device__ __forceinline__ void unpack2(ull v, float& a, float& b) {
    asm("mov.b64 {%0, %1}, %2;" : "=f"(a), "=f"(b) : "l"(v));
}
__device__ __forceinline__ ull fma2(ull a, ull b, ull c) {
    ull d; asm("fma.rn.f32x2 %0, %1, %2, %3;" : "=l"(d) : "l"(a), "l"(b), "l"(c)); return d;
}

__device__ __forceinline__ int edge_at(const void* ei, int is64, long long idx) {
    return is64 ? (int)((const long long*)ei)[idx] : ((const int*)ei)[idx];
}

__device__ __forceinline__ unsigned s2u(const void* p) {
    unsigned a;
    asm("{ .reg .u64 t; cvta.to.shared.u64 t, %1; cvt.u32.u64 %0, t; }" : "=r"(a) : "l"(p));
    return a;
}

// ---------------- prep: detect + deg init + Weff^T + beff ---------------------
__global__ void k_prep(const void* ei,
                       const float* Wz, const float* Wh,
                       const float* Lzw, const float* Lhw,
                       const float* bz, const float* bh,
                       const float* Lzb, const float* Lhb) {
    int b = blockIdx.x, t = threadIdx.x;
    if (b < 391) {
        int i = b * 256 + t;
        if (i < NN) g_deg[i] = 1;           // self loop
    } else if (b == 391) {
        __shared__ int s;
        if (t == 0) s = 1;
        __syncthreads();
        const long long* p = (const long long*)ei;
        for (int i = t; i < 4096; i += 256)
            if ((p[i] >> 32) != 0) s = 0;
        __syncthreads();
        if (t == 0) g_is64 = s;
    } else {
        int idx = (b - 392) * 256 + t;      // [0, 8192)
        int k = idx >> 6, j = idx & 63;
        float acc = 0.f;
        if (j < HID) {
            for (int m = 0; m < HID; m++) acc = fmaf(Wz[k * HID + m], Lzw[m * HID + j], acc);
        } else {
            int jj = j - HID;
            for (int m = 0; m < HID; m++) acc = fmaf(Wh[k * HID + m], Lhw[m * HID + jj], acc);
        }
        g_WT[j * DD + k] = acc;             // transposed store
        if (b == 392 && t < 32) {
            float az = Lzb[t], ah = Lhb[t];
            for (int m = 0; m < HID; m++) {
                az = fmaf(bz[m], Lzw[m * HID + t], az);
                ah = fmaf(bh[m], Lhw[m * HID + t], ah);
            }
            g_beff2[t] = pack2(az, ah);
        }
    }
}

// ---------------- edge conversion + degree count ------------------------------
__global__ void k_deg(const void* __restrict__ ei) {
    int is64 = g_is64;
    int e = blockIdx.x * 256 + threadIdx.x;
    if (e < EE) {
        int s = edge_at(ei, is64, e);
        int d = edge_at(ei, is64, (long long)EE + e);
        g_src32[e] = s;
        g_dst32[e] = d;
        atomicAdd(&g_deg[d], 1);
    }
}

// ---------------- phase-1 scan: block-local exclusive scan of (deg-1) + dinv --
__global__ void k_scan1() {
    __shared__ int warpsums[32];
    int t = threadIdx.x, lane = t & 31, w = t >> 5;
    int i = blockIdx.x * 1024 + t;
    int dg = (i < NN) ? g_deg[i] : 1;
    if (i < NN) g_dinv[i] = rsqrtf((float)dg);
    int v = dg - 1;
    int s = v;
#pragma unroll
    for (int off = 1; off < 32; off <<= 1) {
        int tmp = __shfl_up_sync(0xffffffffu, s, off);
        if (lane >= off) s += tmp;
    }
    if (lane == 31) warpsums[w] = s;
    __syncthreads();
    if (w == 0) {
        int ws = warpsums[lane];
#pragma unroll
        for (int off = 1; off < 32; off <<= 1) {
            int tmp = __shfl_up_sync(0xffffffffu, ws, off);
            if (lane >= off) ws += tmp;
        }
        warpsums[lane] = ws;
    }
    __syncthreads();
    int incl = s + ((w == 0) ? 0 : warpsums[w - 1]);
    if (i < NN) g_off[i] = incl - v;        // block-local exclusive
    if (t == 1023) g_bsum[blockIdx.x] = incl;
}

// ---------------- phase-2: fixup; each block redundantly reduces ALL 98 sums --
#define SB 98
__global__ void k_scan3() {
    __shared__ int spref, stot;
    int t = threadIdx.x, b = blockIdx.x;
    if (t < 32) {
        int v0 = g_bsum[t];
        int v1 = g_bsum[t + 32];
        int v2 = (t + 64 < SB) ? g_bsum[t + 64] : 0;
        int v3 = (t + 96 < SB) ? g_bsum[t + 96] : 0;
        int p = ((t < b) ? v0 : 0) + ((t + 32 < b) ? v1 : 0)
              + ((t + 64 < b) ? v2 : 0) + ((t + 96 < b) ? v3 : 0);
        int q = v0 + v1 + v2 + v3;
#pragma unroll
        for (int off = 16; off; off >>= 1) {
            p += __shfl_down_sync(0xffffffffu, p, off);
            q += __shfl_down_sync(0xffffffffu, q, off);
        }
        if (t == 0) { spref = p; stot = q; }
    }
    __syncthreads();
    int i = b * 1024 + t;
    if (i < NN) {
        int o = g_off[i] + spref;
        g_off[i] = o;
        g_cur[i] = o;
    }
    if (b == SB - 1 && t == 0) g_off[NN] = stot;
}

// ---------------- fused: GEMM×dinv→fp16 (blocks [0,GEMMB)) + CSR scatter ------
#define GEMMB 3125
#define SCATB 6250
__global__ void k_gemm_scat(const float* __restrict__ x) {
    __shared__ float sWT[64 * 130];         // padded rows: stride 130 floats
    int t = threadIdx.x;
    if (blockIdx.x < GEMMB) {
        for (int i = t; i < 64 * 128; i += 256) {
            int j = i >> 7, k = i & 127;
            sWT[j * 130 + k] = g_WT[i];
        }
        __syncthreads();
        int warp = t >> 5, lane = t & 31;
        int n0 = (blockIdx.x * 8 + warp) * 4;       // 4 nodes per warp
        if (n0 >= NN) return;
        const float4* x4 = (const float4*)x;
        ull az[4] = {0, 0, 0, 0}, ah[4] = {0, 0, 0, 0};
        const ull* wzr = (const ull*)&sWT[lane * 130];
        const ull* whr = (const ull*)&sWT[(lane + 32) * 130];
#pragma unroll 4
        for (int k4 = 0; k4 < 32; k4++) {
            float4 a0 = x4[(size_t)(n0 + 0) * 32 + k4];
            float4 a1 = x4[(size_t)(n0 + 1) * 32 + k4];
            float4 a2 = x4[(size_t)(n0 + 2) * 32 + k4];
            float4 a3 = x4[(size_t)(n0 + 3) * 32 + k4];
            ull wz0 = wzr[k4 * 2], wz1 = wzr[k4 * 2 + 1];
            ull wh0 = whr[k4 * 2], wh1 = whr[k4 * 2 + 1];
            const ull* p0 = (const ull*)&a0; const ull* p1 = (const ull*)&a1;
            const ull* p2 = (const ull*)&a2; const ull* p3 = (const ull*)&a3;
            az[0] = fma2(p0[0], wz0, az[0]); az[0] = fma2(p0[1], wz1, az[0]);
            ah[0] = fma2(p0[0], wh0, ah[0]); ah[0] = fma2(p0[1], wh1, ah[0]);
            az[1] = fma2(p1[0], wz0, az[1]); az[1] = fma2(p1[1], wz1, az[1]);
            ah[1] = fma2(p1[0], wh0, ah[1]); ah[1] = fma2(p1[1], wh1, ah[1]);
            az[2] = fma2(p2[0], wz0, az[2]); az[2] = fma2(p2[1], wz1, az[2]);
            ah[2] = fma2(p2[0], wh0, ah[2]); ah[2] = fma2(p2[1], wh1, ah[2]);
            az[3] = fma2(p3[0], wz0, az[3]); az[3] = fma2(p3[1], wz1, az[3]);
            ah[3] = fma2(p3[0], wh0, ah[3]); ah[3] = fma2(p3[1], wh1, ah[3]);
        }
#pragma unroll
        for (int i = 0; i < 4; i++) {
            float dn = g_dinv[n0 + i];
            float zl, zh, hl, hh;
            unpack2(az[i], zl, zh);
            unpack2(ah[i], hl, hh);
            __half2 hv = __floats2half2_rn((zl + zh) * dn, (hl + hh) * dn);
            g_y2h[(size_t)(n0 + i) * 32 + lane] = *(unsigned*)&hv;
        }
    } else {
        int e = (blockIdx.x - GEMMB) * 256 + t;
        if (e < EE) {
            int s = g_src32[e], d = g_dst32[e];
            int pos = atomicAdd(&g_cur[d], 1);
            g_srcs[pos] = s * 32;           // prescaled element offset into g_y2h
        }
    }
}

// ---------------- aggregate (fp16 gathers, fp32 accum) + GRU gates → fp16 H ---
__global__ void k_agg() {
    int warp = (blockIdx.x * blockDim.x + threadIdx.x) >> 5;
    int lane = threadIdx.x & 31;
    if (warp >= NN) return;
    int n = warp;
    unsigned sv = g_y2h[(size_t)n * 32 + lane];     // self term
    float2 f = __half22float2(*(__half2*)&sv);
    float az0 = f.x, ah0 = f.y, az1 = 0.f, ah1 = 0.f;
    int beg = g_off[n], end = g_off[n + 1];
    int idx = beg;
    for (; idx + 1 < end; idx += 2) {
        unsigned v0 = g_y2h[g_srcs[idx] + lane];
        unsigned v1 = g_y2h[g_srcs[idx + 1] + lane];
        float2 f0 = __half22float2(*(__half2*)&v0);
        float2 f1 = __half22float2(*(__half2*)&v1);
        az0 += f0.x; ah0 += f0.y;
        az1 += f1.x; ah1 += f1.y;
    }
    if (idx < end) {
        unsigned v0 = g_y2h[g_srcs[idx] + lane];
        float2 f0 = __half22float2(*(__half2*)&v0);
        az0 += f0.x; ah0 += f0.y;
    }
    float dn = g_dinv[n];
    float bz, bh;
    unpack2(g_beff2[lane], bz, bh);
    float vz = (az0 + az1) * dn + bz;
    float vh = (ah0 + ah1) * dn + bh;
    float z  = 1.f / (1.f + __expf(-vz));
    float ht = tanhf(vh);
    g_Hh[(size_t)n * 32 + lane] = __float2half((1.f - z) * ht);
}

// ---------------- edge MLP via mma.sync m16n8k16: 16-edge tiles per warp ------
// D[16,32] = emb[16,32] @ W1[32,32]; 4 n-tiles x 2 k-steps of HMMA.
__global__ void __launch_bounds__(256) k_edge_mma(
        const float* __restrict__ w1, const float* __restrict__ b1,
        const float* __restrict__ w2, const float* __restrict__ b2,
        float* __restrict__ out) {
    __shared__ __align__(16) __half sEmb[8][16][32];    // 8 warps x (16 edges x 32) = 8KB
    __shared__ float sb1[32], sw2[32];
    __shared__ float sb2v;
    int tid = threadIdx.x, wid = tid >> 5, lane = tid & 31;
    if (tid < 32) { sb1[tid] = b1[tid]; sw2[tid] = w2[tid]; }
    if (tid == 0) sb2v = b2[0];

    int g = lane >> 2, tig = lane & 3;

    // B fragments for W1 (row-major [k][n]); built once per warp from global.
    // b0 = {W1[k0][n], W1[k0+1][n]}, b1 = {W1[k0+8][n], W1[k0+9][n]}, k0 = kt*16+2*tig.
    unsigned Bf[2][4][2];
#pragma unroll
    for (int kt = 0; kt < 2; kt++) {
#pragma unroll
        for (int nt = 0; nt < 4; nt++) {
            int n = nt * 8 + g;
            int k0 = kt * 16 + tig * 2;
            __half2 t0 = __floats2half2_rn(w1[k0 * HID + n],       w1[(k0 + 1) * HID + n]);
            __half2 t1 = __floats2half2_rn(w1[(k0 + 8) * HID + n], w1[(k0 + 9) * HID + n]);
            Bf[kt][nt][0] = *(unsigned*)&t0;
            Bf[kt][nt][1] = *(unsigned*)&t1;
        }
    }
    __syncthreads();

    // gather: 2 lanes per edge; lane covers half hf (16 halves = 32B) of one edge row
    int ebase = (blockIdx.x * 8 + wid) * 16;
    int er = lane >> 1, hf = lane & 1;
    {
        int e = ebase + er;
        int s = g_src32[e], d = g_dst32[e];
        const uint4* Hs = (const uint4*)(g_Hh + (size_t)s * 32) + hf * 2;
        const uint4* Hd = (const uint4*)(g_Hh + (size_t)d * 32) + hf * 2;
        uint4 sa = Hs[0], sbv = Hs[1];
        uint4 da = Hd[0], dbv = Hd[1];
        uint4 r0, r1;
        *(__half2*)&r0.x = __hmul2(*(__half2*)&sa.x, *(__half2*)&da.x);
        *(__half2*)&r0.y = __hmul2(*(__half2*)&sa.y, *(__half2*)&da.y);
        *(__half2*)&r0.z = __hmul2(*(__half2*)&sa.z, *(__half2*)&da.z);
        *(__half2*)&r0.w = __hmul2(*(__half2*)&sa.w, *(__half2*)&da.w);
        *(__half2*)&r1.x = __hmul2(*(__half2*)&sbv.x, *(__half2*)&dbv.x);
        *(__half2*)&r1.y = __hmul2(*(__half2*)&sbv.y, *(__half2*)&dbv.y);
        *(__half2*)&r1.z = __hmul2(*(__half2*)&sbv.z, *(__half2*)&dbv.z);
        *(__half2*)&r1.w = __hmul2(*(__half2*)&sbv.w, *(__half2*)&dbv.w);
        uint4* dst = (uint4*)&sEmb[wid][er][hf * 16];
        dst[0] = r0;
        dst[1] = r1;
    }
    __syncwarp();

    // A fragments via ldmatrix x4: row = lane&15, k-halftile = lane>>4 (16B)
    unsigned A0[4], A1[4];
    {
        unsigned base = s2u(&sEmb[wid][lane & 15][(lane & 16) ? 8 : 0]);
        asm volatile("ldmatrix.sync.aligned.m8n8.x4.shared.b16 {%0,%1,%2,%3}, [%4];"
                     : "=r"(A0[0]), "=r"(A0[1]), "=r"(A0[2]), "=r"(A0[3]) : "r"(base));
        asm volatile("ldmatrix.sync.aligned.m8n8.x4.shared.b16 {%0,%1,%2,%3}, [%4];"
                     : "=r"(A1[0]), "=r"(A1[1]), "=r"(A1[2]), "=r"(A1[3]) : "r"(base + 32));
    }

    float D[4][4];
#pragma unroll
    for (int nt = 0; nt < 4; nt++) {
        D[nt][0] = D[nt][1] = D[nt][2] = D[nt][3] = 0.f;
        asm volatile(
            "mma.sync.aligned.m16n8k16.row.col.f32.f16.f16.f32 "
            "{%0,%1,%2,%3}, {%4,%5,%6,%7}, {%8,%9}, {%0,%1,%2,%3};"
            : "+f"(D[nt][0]), "+f"(D[nt][1]), "+f"(D[nt][2]), "+f"(D[nt][3])
            : "r"(A0[0]), "r"(A0[1]), "r"(A0[2]), "r"(A0[3]),
              "r"(Bf[0][nt][0]), "r"(Bf[0][nt][1]));
        asm volatile(
            "mma.sync.aligned.m16n8k16.row.col.f32.f16.f16.f32 "
            "{%0,%1,%2,%3}, {%4,%5,%6,%7}, {%8,%9}, {%0,%1,%2,%3};"
            : "+f"(D[nt][0]), "+f"(D[nt][1]), "+f"(D[nt][2]), "+f"(D[nt][3])
            : "r"(A1[0]), "r"(A1[1]), "r"(A1[2]), "r"(A1[3]),
              "r"(Bf[1][nt][0]), "r"(Bf[1][nt][1]));
    }

    // epilogue: lane holds rows {g, g+8}, cols {nt*8 + 2*tig, +1}
    float l0 = 0.f, l1 = 0.f;
#pragma unroll
    for (int nt = 0; nt < 4; nt++) {
        int c0 = nt * 8 + tig * 2;
        float w20 = sw2[c0], w21 = sw2[c0 + 1];
        float bb0 = sb1[c0], bb1 = sb1[c0 + 1];
        l0 = fmaf(fmaxf(D[nt][0] + bb0, 0.f), w20, l0);
        l0 = fmaf(fmaxf(D[nt][1] + bb1, 0.f), w21, l0);
        l1 = fmaf(fmaxf(D[nt][2] + bb0, 0.f), w20, l1);
        l1 = fmaf(fmaxf(D[nt][3] + bb1, 0.f), w21, l1);
    }
    l0 += __shfl_xor_sync(0xffffffffu, l0, 1);
    l0 += __shfl_xor_sync(0xffffffffu, l0, 2);
    l1 += __shfl_xor_sync(0xffffffffu, l1, 1);
    l1 += __shfl_xor_sync(0xffffffffu, l1, 2);
    if (tig == 0) {
        out[ebase + g]     = 1.f / (1.f + __expf(-(l0 + sb2v)));
        out[ebase + g + 8] = 1.f / (1.f + __expf(-(l1 + sb2v)));
    }
}

// ---------------- launch ------------------------------------------------------
extern "C" void kernel_launch(void* const* d_in, const int* in_sizes, int n_in,
                              void* d_out, int out_size) {
    const float* x   = (const float*)d_in[0];
    const void*  ei  = d_in[1];
    const float* Wz  = (const float*)d_in[2];
    const float* bz  = (const float*)d_in[3];
    const float* Wh  = (const float*)d_in[6];
    const float* bh  = (const float*)d_in[7];
    const float* Lzw = (const float*)d_in[8];
    const float* Lzb = (const float*)d_in[9];
    const float* Lhw = (const float*)d_in[12];
    const float* Lhb = (const float*)d_in[13];
    const float* w1  = (const float*)d_in[14];
    const float* b1  = (const float*)d_in[15];
    const float* w2  = (const float*)d_in[16];
    const float* b2  = (const float*)d_in[17];
    float* out = (float*)d_out;

    k_prep<<<424, 256>>>(ei, Wz, Wh, Lzw, Lhw, bz, bh, Lzb, Lhb);
    k_deg<<<6250, 256>>>(ei);
    k_scan1<<<98, 1024>>>();
    k_scan3<<<SB, 1024>>>();
    k_gemm_scat<<<GEMMB + SCATB, 256>>>(x);
    k_agg<<<(NN * 32 + 255) / 256, 256>>>();
    k_edge_mma<<<EE / 128, 256>>>(w1, b1, w2, b2, out);
}

// round 15
// speedup vs baseline: 1.5739x; 1.2219x over previous
#include <cuda_runtime.h>
#include <cuda_fp16.h>
#include <math.h>

#define NN 100000
#define EE 1600000
#define DD 128
#define HID 32

typedef unsigned long long ull;

// ---------------- scratch (device globals) ------------------------------------
__device__ int      g_is64;
__device__ int      g_deg[NN];
__device__ float    g_dinv[NN];
__device__ int      g_off[NN + 1];
__device__ int      g_cur[NN];
__device__ int      g_src32[EE];
__device__ int      g_dst32[EE];
__device__ int      g_srcs[EE];             // CSR: prescaled src element offsets (s*32)
__device__ unsigned g_y2h[(size_t)NN * 32]; // half2(z,h) per (node,feature); pre-scaled by dinv
__device__ __half   g_Hh[(size_t)NN * 32];  // H in fp16, 64B rows
__device__ float    g_WT[64 * DD];          // WeffT[j][k], j: 0..31=z, 32..63=h
__device__ ull      g_beff2[32];            // packed (bz_eff, bh_eff) fp32
__device__ int      g_bsum[128];

// ---------------- helpers ------------------------------------------------------
__device__ __forceinline__ ull pack2(float a, float b) {
    ull r; asm("mov.b64 %0, {%1, %2};" : "=l"(r) : "f"(a), "f"(b)); return r;
}
__device__ __forceinline__ void unpack2(ull v, float& a, float& b) {
    asm("mov.b64 {%0, %1}, %2;" : "=f"(a), "=f"(b) : "l"(v));
}
__device__ __forceinline__ int edge_at(const void* ei, int is64, long long idx) {
    return is64 ? (int)((const long long*)ei)[idx] : ((const int*)ei)[idx];
}
__device__ __forceinline__ unsigned s2u(const void* p) {
    unsigned a;
    asm("{ .reg .u64 t; cvta.to.shared.u64 t, %1; cvt.u32.u64 %0, t; }" : "=r"(a) : "l"(p));
    return a;
}

// ---------------- prep: detect + deg init + Weff^T + beff ---------------------
__global__ void k_prep(const void* ei,
                       const float* Wz, const float* Wh,
                       const float* Lzw, const float* Lhw,
                       const float* bz, const float* bh,
                       const float* Lzb, const float* Lhb) {
    int b = blockIdx.x, t = threadIdx.x;
    if (b < 391) {
        int i = b * 256 + t;
        if (i < NN) g_deg[i] = 1;           // self loop
    } else if (b == 391) {
        __shared__ int s;
        if (t == 0) s = 1;
        __syncthreads();
        const long long* p = (const long long*)ei;
        for (int i = t; i < 4096; i += 256)
            if ((p[i] >> 32) != 0) s = 0;
        __syncthreads();
        if (t == 0) g_is64 = s;
    } else {
        int idx = (b - 392) * 256 + t;      // [0, 8192)
        int k = idx >> 6, j = idx & 63;
        float acc = 0.f;
        if (j < HID) {
            for (int m = 0; m < HID; m++) acc = fmaf(Wz[k * HID + m], Lzw[m * HID + j], acc);
        } else {
            int jj = j - HID;
            for (int m = 0; m < HID; m++) acc = fmaf(Wh[k * HID + m], Lhw[m * HID + jj], acc);
        }
        g_WT[j * DD + k] = acc;             // transposed store [j][k]
        if (b == 392 && t < 32) {
            float az = Lzb[t], ah = Lhb[t];
            for (int m = 0; m < HID; m++) {
                az = fmaf(bz[m], Lzw[m * HID + t], az);
                ah = fmaf(bh[m], Lhw[m * HID + t], ah);
            }
            g_beff2[t] = pack2(az, ah);
        }
    }
}

// ---------------- edge conversion + degree count ------------------------------
__global__ void k_deg(const void* __restrict__ ei) {
    int is64 = g_is64;
    int e = blockIdx.x * 256 + threadIdx.x;
    if (e < EE) {
        int s = edge_at(ei, is64, e);
        int d = edge_at(ei, is64, (long long)EE + e);
        g_src32[e] = s;
        g_dst32[e] = d;
        atomicAdd(&g_deg[d], 1);
    }
}

// ---------------- phase-1 scan: block-local exclusive scan of (deg-1) + dinv --
__global__ void k_scan1() {
    __shared__ int warpsums[32];
    int t = threadIdx.x, lane = t & 31, w = t >> 5;
    int i = blockIdx.x * 1024 + t;
    int dg = (i < NN) ? g_deg[i] : 1;
    if (i < NN) g_dinv[i] = rsqrtf((float)dg);
    int v = dg - 1;
    int s = v;
#pragma unroll
    for (int off = 1; off < 32; off <<= 1) {
        int tmp = __shfl_up_sync(0xffffffffu, s, off);
        if (lane >= off) s += tmp;
    }
    if (lane == 31) warpsums[w] = s;
    __syncthreads();
    if (w == 0) {
        int ws = warpsums[lane];
#pragma unroll
        for (int off = 1; off < 32; off <<= 1) {
            int tmp = __shfl_up_sync(0xffffffffu, ws, off);
            if (lane >= off) ws += tmp;
        }
        warpsums[lane] = ws;
    }
    __syncthreads();
    int incl = s + ((w == 0) ? 0 : warpsums[w - 1]);
    if (i < NN) g_off[i] = incl - v;        // block-local exclusive
    if (t == 1023) g_bsum[blockIdx.x] = incl;
}

// ---------------- phase-2: fixup; each block redundantly reduces ALL 98 sums --
#define SB 98
__global__ void k_scan3() {
    __shared__ int spref, stot;
    int t = threadIdx.x, b = blockIdx.x;
    if (t < 32) {
        int v0 = g_bsum[t];
        int v1 = g_bsum[t + 32];
        int v2 = (t + 64 < SB) ? g_bsum[t + 64] : 0;
        int v3 = (t + 96 < SB) ? g_bsum[t + 96] : 0;
        int p = ((t < b) ? v0 : 0) + ((t + 32 < b) ? v1 : 0)
              + ((t + 64 < b) ? v2 : 0) + ((t + 96 < b) ? v3 : 0);
        int q = v0 + v1 + v2 + v3;
#pragma unroll
        for (int off = 16; off; off >>= 1) {
            p += __shfl_down_sync(0xffffffffu, p, off);
            q += __shfl_down_sync(0xffffffffu, q, off);
        }
        if (t == 0) { spref = p; stot = q; }
    }
    __syncthreads();
    int i = b * 1024 + t;
    if (i < NN) {
        int o = g_off[i] + spref;
        g_off[i] = o;
        g_cur[i] = o;
    }
    if (b == SB - 1 && t == 0) g_off[NN] = stot;
}

// ---------------- fused: HMMA node GEMM (blocks [0,GEMMB)) + CSR scatter ------
// y[16n,64] = x[16n,128]@Weff[128,64] per warp-tile; dinv folded; fp16 out.
// smem rows are 256B with 16B-chunk XOR swizzle: chunk' = chunk ^ (row&7).
#define GEMMB 1563              // ceil(6250 warp-tiles / 4 warps per 128-thr block)
#define SCATB 12500
__global__ void __launch_bounds__(128) k_gemm_scat(const float* __restrict__ x) {
    if (blockIdx.x < GEMMB) {
        __shared__ __align__(16) __half sB[64 * 128];     // Weff fp16, swizzled (16KB)
        __shared__ __align__(16) __half sA[4][16 * 128];  // per-warp x tiles (16KB)
        int tid = threadIdx.x, wid = tid >> 5, lane = tid & 31;

        // fill B: g_WT [64][128] fp32 -> fp16 swizzled
        for (int idx = tid; idx < 2048; idx += 128) {     // 2048 float4
            int row = idx >> 5, f4 = idx & 31;
            float4 v = ((const float4*)g_WT)[idx];
            __half2 h0 = __floats2half2_rn(v.x, v.y);
            __half2 h1 = __floats2half2_rn(v.z, v.w);
            unsigned off = (unsigned)(row * 256 + (((f4 >> 1) ^ (row & 7)) << 4) + ((f4 & 1) << 3));
            *(unsigned*)((char*)sB + off)     = *(unsigned*)&h0;
            *(unsigned*)((char*)sB + off + 4) = *(unsigned*)&h1;
        }
        __syncthreads();

        int wt = blockIdx.x * 4 + wid;                    // warp-tile id
        if (wt >= 6250) return;
        int n0 = wt * 16;

        // fill A: 16 rows, lane = float4 index within row (coalesced 512B/row)
        const float4* x4 = (const float4*)x;
#pragma unroll
        for (int ii = 0; ii < 16; ii++) {
            float4 v = x4[(size_t)(n0 + ii) * 32 + lane];
            __half2 h0 = __floats2half2_rn(v.x, v.y);
            __half2 h1 = __floats2half2_rn(v.z, v.w);
            unsigned off = (unsigned)(ii * 256 + (((lane >> 1) ^ (ii & 7)) << 4) + ((lane & 1) << 3));
            *(unsigned*)((char*)sA[wid] + off)     = *(unsigned*)&h0;
            *(unsigned*)((char*)sA[wid] + off + 4) = *(unsigned*)&h1;
        }
        __syncwarp();

        // A fragments: 8 k-tiles of m16k16
        unsigned Af[8][4];
        unsigned sA_u = s2u(sA[wid]);
        {
            int r = lane & 15;
#pragma unroll
            for (int kt = 0; kt < 8; kt++) {
                unsigned chunk = (unsigned)(2 * kt + ((lane & 16) ? 1 : 0));
                unsigned addr = sA_u + (unsigned)(r * 256) + ((chunk ^ (unsigned)(r & 7)) << 4);
                asm volatile("ldmatrix.sync.aligned.m8n8.x4.shared.b16 {%0,%1,%2,%3}, [%4];"
                             : "=r"(Af[kt][0]), "=r"(Af[kt][1]), "=r"(Af[kt][2]), "=r"(Af[kt][3])
                             : "r"(addr));
            }
        }

        unsigned sB_u = s2u(sB);
        int g = lane >> 2, tig = lane & 3;
        int rB = lane & 7;
        unsigned bhalf = (lane & 8) ? 1u : 0u;

#pragma unroll
        for (int p = 0; p < 4; p++) {                     // z cols nt=p, h cols nt=p+4
            float Dz[4] = {0.f, 0.f, 0.f, 0.f};
            float Dh[4] = {0.f, 0.f, 0.f, 0.f};
#pragma unroll
            for (int kt = 0; kt < 8; kt++) {
                unsigned chunk = (unsigned)(2 * kt) + bhalf;
                unsigned swz = ((chunk ^ (unsigned)rB) << 4);
                unsigned az_addr = sB_u + (unsigned)((p * 8 + rB) * 256) + swz;
                unsigned ah_addr = sB_u + (unsigned)(((p + 4) * 8 + rB) * 256) + swz;
                unsigned Bz[2], Bh[2];
                asm volatile("ldmatrix.sync.aligned.m8n8.x2.shared.b16 {%0,%1}, [%2];"
                             : "=r"(Bz[0]), "=r"(Bz[1]) : "r"(az_addr));
                asm volatile("ldmatrix.sync.aligned.m8n8.x2.shared.b16 {%0,%1}, [%2];"
                             : "=r"(Bh[0]), "=r"(Bh[1]) : "r"(ah_addr));
                asm volatile(
                    "mma.sync.aligned.m16n8k16.row.col.f32.f16.f16.f32 "
                    "{%0,%1,%2,%3}, {%4,%5,%6,%7}, {%8,%9}, {%0,%1,%2,%3};"
                    : "+f"(Dz[0]), "+f"(Dz[1]), "+f"(Dz[2]), "+f"(Dz[3])
                    : "r"(Af[kt][0]), "r"(Af[kt][1]), "r"(Af[kt][2]), "r"(Af[kt][3]),
                      "r"(Bz[0]), "r"(Bz[1]));
                asm volatile(
                    "mma.sync.aligned.m16n8k16.row.col.f32.f16.f16.f32 "
                    "{%0,%1,%2,%3}, {%4,%5,%6,%7}, {%8,%9}, {%0,%1,%2,%3};"
                    : "+f"(Dh[0]), "+f"(Dh[1]), "+f"(Dh[2]), "+f"(Dh[3])
                    : "r"(Af[kt][0]), "r"(Af[kt][1]), "r"(Af[kt][2]), "r"(Af[kt][3]),
                      "r"(Bh[0]), "r"(Bh[1]));
            }
            // epilogue: lane holds rows {g, g+8}, cols {p*8+2tig, +1}; pair (z,h) -> half2
            int c0 = p * 8 + tig * 2;
            float dn0 = g_dinv[n0 + g];
            float dn1 = g_dinv[n0 + g + 8];
            __half2 a0 = __floats2half2_rn(Dz[0] * dn0, Dh[0] * dn0);
            __half2 a1 = __floats2half2_rn(Dz[1] * dn0, Dh[1] * dn0);
            __half2 b0 = __floats2half2_rn(Dz[2] * dn1, Dh[2] * dn1);
            __half2 b1 = __floats2half2_rn(Dz[3] * dn1, Dh[3] * dn1);
            unsigned ua0 = *(unsigned*)&a0, ua1 = *(unsigned*)&a1;
            unsigned ub0 = *(unsigned*)&b0, ub1 = *(unsigned*)&b1;
            *(ull*)&g_y2h[(size_t)(n0 + g) * 32 + c0]     = ((ull)ua1 << 32) | ua0;
            *(ull*)&g_y2h[(size_t)(n0 + g + 8) * 32 + c0] = ((ull)ub1 << 32) | ub0;
        }
    } else {
        int e = (blockIdx.x - GEMMB) * 128 + threadIdx.x;
        if (e < EE) {
            int s = g_src32[e], d = g_dst32[e];
            int pos = atomicAdd(&g_cur[d], 1);
            g_srcs[pos] = s * 32;           // prescaled element offset into g_y2h
        }
    }
}

// ---------------- aggregate (fp16 gathers, fp32 accum) + GRU gates → fp16 H ---
__global__ void k_agg() {
    int warp = (blockIdx.x * blockDim.x + threadIdx.x) >> 5;
    int lane = threadIdx.x & 31;
    if (warp >= NN) return;
    int n = warp;
    unsigned sv = g_y2h[(size_t)n * 32 + lane];     // self term
    float2 f = __half22float2(*(__half2*)&sv);
    float az0 = f.x, ah0 = f.y, az1 = 0.f, ah1 = 0.f;
    int beg = g_off[n], end = g_off[n + 1];
    int idx = beg;
    for (; idx + 1 < end; idx += 2) {
        unsigned v0 = g_y2h[g_srcs[idx] + lane];
        unsigned v1 = g_y2h[g_srcs[idx + 1] + lane];
        float2 f0 = __half22float2(*(__half2*)&v0);
        float2 f1 = __half22float2(*(__half2*)&v1);
        az0 += f0.x; ah0 += f0.y;
        az1 += f1.x; ah1 += f1.y;
    }
    if (idx < end) {
        unsigned v0 = g_y2h[g_srcs[idx] + lane];
        float2 f0 = __half22float2(*(__half2*)&v0);
        az0 += f0.x; ah0 += f0.y;
    }
    float dn = g_dinv[n];
    float bz, bh;
    unpack2(g_beff2[lane], bz, bh);
    float vz = (az0 + az1) * dn + bz;
    float vh = (ah0 + ah1) * dn + bh;
    float z  = 1.f / (1.f + __expf(-vz));
    float ht = tanhf(vh);
    g_Hh[(size_t)n * 32 + lane] = __float2half((1.f - z) * ht);
}

// ---------------- edge MLP via mma.sync m16n8k16 (R14-proven) -----------------
__global__ void __launch_bounds__(256) k_edge_mma(
        const float* __restrict__ w1, const float* __restrict__ b1,
        const float* __restrict__ w2, const float* __restrict__ b2,
        float* __restrict__ out) {
    __shared__ __align__(16) __half sEmb[8][16][32];
    __shared__ float sb1[32], sw2[32];
    __shared__ float sb2v;
    int tid = threadIdx.x, wid = tid >> 5, lane = tid & 31;
    if (tid < 32) { sb1[tid] = b1[tid]; sw2[tid] = w2[tid]; }
    if (tid == 0) sb2v = b2[0];

    int g = lane >> 2, tig = lane & 3;

    unsigned Bf[2][4][2];
#pragma unroll
    for (int kt = 0; kt < 2; kt++) {
#pragma unroll
        for (int nt = 0; nt < 4; nt++) {
            int n = nt * 8 + g;
            int k0 = kt * 16 + tig * 2;
            __half2 t0 = __floats2half2_rn(w1[k0 * HID + n],       w1[(k0 + 1) * HID + n]);
            __half2 t1 = __floats2half2_rn(w1[(k0 + 8) * HID + n], w1[(k0 + 9) * HID + n]);
            Bf[kt][nt][0] = *(unsigned*)&t0;
            Bf[kt][nt][1] = *(unsigned*)&t1;
        }
    }
    __syncthreads();

    int ebase = (blockIdx.x * 8 + wid) * 16;
    int er = lane >> 1, hf = lane & 1;
    {
        int e = ebase + er;
        int s = g_src32[e], d = g_dst32[e];
        const uint4* Hs = (const uint4*)(g_Hh + (size_t)s * 32) + hf * 2;
        const uint4* Hd = (const uint4*)(g_Hh + (size_t)d * 32) + hf * 2;
        uint4 sa = Hs[0], sbv = Hs[1];
        uint4 da = Hd[0], dbv = Hd[1];
        uint4 r0, r1;
        *(__half2*)&r0.x = __hmul2(*(__half2*)&sa.x, *(__half2*)&da.x);
        *(__half2*)&r0.y = __hmul2(*(__half2*)&sa.y, *(__half2*)&da.y);
        *(__half2*)&r0.z = __hmul2(*(__half2*)&sa.z, *(__half2*)&da.z);
        *(__half2*)&r0.w = __hmul2(*(__half2*)&sa.w, *(__half2*)&da.w);
        *(__half2*)&r1.x = __hmul2(*(__half2*)&sbv.x, *(__half2*)&dbv.x);
        *(__half2*)&r1.y = __hmul2(*(__half2*)&sbv.y, *(__half2*)&dbv.y);
        *(__half2*)&r1.z = __hmul2(*(__half2*)&sbv.z, *(__half2*)&dbv.z);
        *(__half2*)&r1.w = __hmul2(*(__half2*)&sbv.w, *(__half2*)&dbv.w);
        uint4* dst = (uint4*)&sEmb[wid][er][hf * 16];
        dst[0] = r0;
        dst[1] = r1;
    }
    __syncwarp();

    unsigned A0[4], A1[4];
    {
        unsigned base = s2u(&sEmb[wid][lane & 15][(lane & 16) ? 8 : 0]);
        asm volatile("ldmatrix.sync.aligned.m8n8.x4.shared.b16 {%0,%1,%2,%3}, [%4];"
                     : "=r"(A0[0]), "=r"(A0[1]), "=r"(A0[2]), "=r"(A0[3]) : "r"(base));
        asm volatile("ldmatrix.sync.aligned.m8n8.x4.shared.b16 {%0,%1,%2,%3}, [%4];"
                     : "=r"(A1[0]), "=r"(A1[1]), "=r"(A1[2]), "=r"(A1[3]) : "r"(base + 32));
    }

    float D[4][4];
#pragma unroll
    for (int nt = 0; nt < 4; nt++) {
        D[nt][0] = D[nt][1] = D[nt][2] = D[nt][3] = 0.f;
        asm volatile(
            "mma.sync.aligned.m16n8k16.row.col.f32.f16.f16.f32 "
            "{%0,%1,%2,%3}, {%4,%5,%6,%7}, {%8,%9}, {%0,%1,%2,%3};"
            : "+f"(D[nt][0]), "+f"(D[nt][1]), "+f"(D[nt][2]), "+f"(D[nt][3])
            : "r"(A0[0]), "r"(A0[1]), "r"(A0[2]), "r"(A0[3]),
              "r"(Bf[0][nt][0]), "r"(Bf[0][nt][1]));
        asm volatile(
            "mma.sync.aligned.m16n8k16.row.col.f32.f16.f16.f32 "
            "{%0,%1,%2,%3}, {%4,%5,%6,%7}, {%8,%9}, {%0,%1,%2,%3};"
            : "+f"(D[nt][0]), "+f"(D[nt][1]), "+f"(D[nt][2]), "+f"(D[nt][3])
            : "r"(A1[0]), "r"(A1[1]), "r"(A1[2]), "r"(A1[3]),
              "r"(Bf[1][nt][0]), "r"(Bf[1][nt][1]));
    }

    float l0 = 0.f, l1 = 0.f;
#pragma unroll
    for (int nt = 0; nt < 4; nt++) {
        int c0 = nt * 8 + tig * 2;
        float w20 = sw2[c0], w21 = sw2[c0 + 1];
        float bb0 = sb1[c0], bb1 = sb1[c0 + 1];
        l0 = fmaf(fmaxf(D[nt][0] + bb0, 0.f), w20, l0);
        l0 = fmaf(fmaxf(D[nt][1] + bb1, 0.f), w21, l0);
        l1 = fmaf(fmaxf(D[nt][2] + bb0, 0.f), w20, l1);
        l1 = fmaf(fmaxf(D[nt][3] + bb1, 0.f), w21, l1);
    }
    l0 += __shfl_xor_sync(0xffffffffu, l0, 1);
    l0 += __shfl_xor_sync(0xffffffffu, l0, 2);
    l1 += __shfl_xor_sync(0xffffffffu, l1, 1);
    l1 += __shfl_xor_sync(0xffffffffu, l1, 2);
    if (tig == 0) {
        out[ebase + g]     = 1.f / (1.f + __expf(-(l0 + sb2v)));
        out[ebase + g + 8] = 1.f / (1.f + __expf(-(l1 + sb2v)));
    }
}

// ---------------- launch ------------------------------------------------------
extern "C" void kernel_launch(void* const* d_in, const int* in_sizes, int n_in,
                              void* d_out, int out_size) {
    const float* x   = (const float*)d_in[0];
    const void*  ei  = d_in[1];
    const float* Wz  = (const float*)d_in[2];
    const float* bz  = (const float*)d_in[3];
    const float* Wh  = (const float*)d_in[6];
    const float* bh  = (const float*)d_in[7];
    const float* Lzw = (const float*)d_in[8];
    const float* Lzb = (const float*)d_in[9];
    const float* Lhw = (const float*)d_in[12];
    const float* Lhb = (const float*)d_in[13];
    const float* w1  = (const float*)d_in[14];
    const float* b1  = (const float*)d_in[15];
    const float* w2  = (const float*)d_in[16];
    const float* b2  = (const float*)d_in[17];
    float* out = (float*)d_out;

    k_prep<<<424, 256>>>(ei, Wz, Wh, Lzw, Lhw, bz, bh, Lzb, Lhb);
    k_deg<<<6250, 256>>>(ei);
    k_scan1<<<98, 1024>>>();
    k_scan3<<<SB, 1024>>>();
    k_gemm_scat<<<GEMMB + SCATB, 128>>>(x);
    k_agg<<<(NN * 32 + 255) / 256, 256>>>();
    k_edge_mma<<<EE / 128, 256>>>(w1, b1, w2, b2, out);
}